// round 3
// baseline (speedup 1.0000x reference)
#include <cuda_runtime.h>
#include <math.h>
#include <stdint.h>

// Problem constants
#define DD    512
#define KC    1024
#define QL    8
#define NTOK  16384
#define MT    64          // tokens per CTA
#define CCH   128         // codes per chunk
#define DS    32          // d-slice per smem stage
#define NCTA  (NTOK / MT) // 256

// Paired (d/2-interleaved) smem strides, in floats
#define RP    132         // res: [256 dp][64 tok * 2] + pad (mult of 4 for 16B LDS)
#define PSTR  264         // cbs: [16 dp][128 code * 2] + pad (mult of 4)

#define IDXOFF ((size_t)NTOK * DD)           // 8388608
#define SCLOFF (IDXOFF + (size_t)NTOK * QL)  // 8519680

// packed f32x2 FMA: d.lo = fma(a.lo,b.lo,d.lo); d.hi likewise (sm_100+)
#define FMA2(acc, a, b) \
    asm("fma.rn.f32x2 %0, %1, %2, %0;" : "+l"(acc) : "l"(a), "l"(b))

// Scratch (static device arrays; no cudaMalloc anywhere)
__device__ float  g_csq[QL * KC];
__device__ int    g_cnt[QL * KC];
__device__ double g_commit[QL];
__device__ float  g_qsum[(size_t)NTOK * DD];

// ---------------------------------------------------------------------------
__global__ void rvq_prep(const float* __restrict__ cb) {
    int i = blockIdx.x * blockDim.x + threadIdx.x;
    if (i < QL * KC) {
        const float* c = cb + (size_t)i * DD;
        float s = 0.f;
        for (int d = 0; d < DD; ++d) { float v = c[d]; s += v * v; }
        g_csq[i] = s;
        g_cnt[i] = 0;
    }
    if (i < QL) g_commit[i] = 0.0;
}

// ---------------------------------------------------------------------------
// Fused main kernel: residual tile resident in smem (d-pair interleaved)
// across all 8 levels. Distance GEMM uses packed fma.rn.f32x2 (2 MACs/issue).
// ---------------------------------------------------------------------------
__global__ void __launch_bounds__(256, 1)
rvq_main(const float* __restrict__ x, const float* __restrict__ cb,
         float* __restrict__ out) {
    extern __shared__ char smraw[];
    float* res  = (float*)smraw;                    // [256 dp][RP]
    float* cbs  = res + (DD / 2) * RP;              // [16 dp][PSTR]
    float* redv = cbs + (DS / 2) * PSTR;            // [16][64]
    int*   redi = (int*)(redv + 16 * 64);           // [16][64]
    float* rsqp = (float*)(redi + 16 * 64);         // [4][64]
    float* rsq  = rsqp + 4 * 64;                    // [64]
    int*   idxs = (int*)(rsq + 64);                 // [64]

    const int tid  = threadIdx.x;
    const int tok0 = blockIdx.x * MT;

    // GEMM mapping: 16 token-groups x 16 code-groups
    const int tg = tid & 15;   // tokens tg*4 .. tg*4+3
    const int cg = tid >> 4;   // codes  cg*8 .. cg*8+7 within chunk

    // update-phase mapping: 4 threads per token
    const int tsub  = tid & 3;
    const int tloc  = tid >> 2;         // 0..63
    const int dbase = tsub * 128;

    // ---- initial load: x -> res (d-pair interleaved) + rsq partials
    {
        const float* xp = x + (size_t)(tok0 + tloc) * DD + dbase;
        float s = 0.f;
        #pragma unroll 4
        for (int j = 0; j < 128; j += 4) {
            float4 v = *(const float4*)(xp + j);
            int dp = (dbase + j) >> 1;
            *(float2*)&res[dp * RP + tloc * 2]       = make_float2(v.x, v.y);
            *(float2*)&res[(dp + 1) * RP + tloc * 2] = make_float2(v.z, v.w);
            s += v.x * v.x; s += v.y * v.y; s += v.z * v.z; s += v.w * v.w;
        }
        rsqp[tsub * 64 + tloc] = s;
    }
    __syncthreads();
    if (tid < MT)
        rsq[tid] = ((rsqp[tid] + rsqp[64 + tid]) + rsqp[128 + tid]) + rsqp[192 + tid];

    for (int l = 0; l < QL; ++l) {
        const float* cbl  = cb + (size_t)l * KC * DD;
        const float* csql = g_csq + l * KC;

        float bestv[4]; int besti[4];
        #pragma unroll
        for (int i = 0; i < 4; ++i) { bestv[i] = __int_as_float(0x7f800000); besti[i] = 0; }

        unsigned long long acc[4][8];
        float4 pf[4];
        {   // prefetch slice 0 of chunk 0
            #pragma unroll
            for (int i = 0; i < 4; ++i) {
                int f4 = i * 256 + tid;
                int code = f4 >> 3, seg = f4 & 7;
                pf[i] = *(const float4*)(cbl + (size_t)code * DD + (seg << 2));
            }
        }

        #pragma unroll 1
        for (int step = 0; step < (KC / CCH) * (DD / DS); ++step) {
            const int kc = (step >> 4) * CCH;
            const int sl = step & 15;

            if (sl == 0) {
                #pragma unroll
                for (int i = 0; i < 4; ++i)
                    #pragma unroll
                    for (int j = 0; j < 8; ++j) acc[i][j] = 0ULL;
            }

            __syncthreads();   // previous compute done before overwriting cbs
            #pragma unroll
            for (int i = 0; i < 4; ++i) {
                int f4 = i * 256 + tid;
                int code = f4 >> 3, seg = f4 & 7;
                int dpl = seg << 1;   // 4 dims -> local dp, dp+1
                *(float2*)&cbs[dpl * PSTR + code * 2]       = make_float2(pf[i].x, pf[i].y);
                *(float2*)&cbs[(dpl + 1) * PSTR + code * 2] = make_float2(pf[i].z, pf[i].w);
            }
            __syncthreads();

            // prefetch next slice (global latency hidden under FMA loop)
            if (step + 1 < (KC / CCH) * (DD / DS)) {
                const int nkc = ((step + 1) >> 4) * CCH;
                const int nd0 = ((step + 1) & 15) * DS;
                #pragma unroll
                for (int i = 0; i < 4; ++i) {
                    int f4 = i * 256 + tid;
                    int code = f4 >> 3, seg = f4 & 7;
                    pf[i] = *(const float4*)(cbl + (size_t)(nkc + code) * DD + nd0 + (seg << 2));
                }
            }

            const int d0p = sl * (DS / 2);
            #pragma unroll 4
            for (int ddp = 0; ddp < DS / 2; ++ddp) {
                const float* ap = &res[(d0p + ddp) * RP + (tg << 3)];
                const float* bp = &cbs[ddp * PSTR + (cg << 4)];
                ulonglong2 A0 = *(const ulonglong2*)ap;        // tok pairs 0,1
                ulonglong2 A1 = *(const ulonglong2*)(ap + 4);  // tok pairs 2,3
                ulonglong2 B0 = *(const ulonglong2*)bp;        // code pairs 0,1
                ulonglong2 B1 = *(const ulonglong2*)(bp + 4);  // 2,3
                ulonglong2 B2 = *(const ulonglong2*)(bp + 8);  // 4,5
                ulonglong2 B3 = *(const ulonglong2*)(bp + 12); // 6,7
                unsigned long long pa[4] = {A0.x, A0.y, A1.x, A1.y};
                unsigned long long pb[8] = {B0.x, B0.y, B1.x, B1.y,
                                            B2.x, B2.y, B3.x, B3.y};
                #pragma unroll
                for (int i = 0; i < 4; ++i)
                    #pragma unroll
                    for (int j = 0; j < 8; ++j)
                        FMA2(acc[i][j], pa[i], pb[j]);
            }

            if (sl == 15) {
                // dot = even-dim sum + odd-dim sum; dist = fl(fl(rsq-2*dot)+csq)
                #pragma unroll
                for (int i = 0; i < 4; ++i) {
                    float rq = rsq[(tg << 2) + i];
                    #pragma unroll
                    for (int j = 0; j < 8; ++j) {
                        float lo = __uint_as_float((unsigned)acc[i][j]);
                        float hi = __uint_as_float((unsigned)(acc[i][j] >> 32));
                        float dot = lo + hi;
                        int code = kc + (cg << 3) + j;
                        float dist = fmaf(-2.f, dot, rq) + csql[code];
                        if (dist < bestv[i]) { bestv[i] = dist; besti[i] = code; }
                    }
                }
            }
        }

        // ---- cross-thread argmin reduce (lowest index wins ties)
        __syncthreads();
        #pragma unroll
        for (int i = 0; i < 4; ++i) {
            redv[cg * 64 + (tg << 2) + i] = bestv[i];
            redi[cg * 64 + (tg << 2) + i] = besti[i];
        }
        __syncthreads();
        if (tid < MT) {
            float bv = redv[tid]; int bi = redi[tid];
            #pragma unroll 1
            for (int c = 1; c < 16; ++c) {
                float v = redv[c * 64 + tid]; int ix = redi[c * 64 + tid];
                if (v < bv || (v == bv && ix < bi)) { bv = v; bi = ix; }
            }
            idxs[tid] = bi;
            out[IDXOFF + (size_t)(tok0 + tid) * QL + l] = (float)bi;
            atomicAdd(&g_cnt[l * KC + bi], 1);
        }
        __syncthreads();

        // ---- gather + residual/qsum update + rsq partials for next level
        {
            const int myidx = idxs[tloc];
            const float* qv = cbl + (size_t)myidx * DD + dbase;
            float* qs = g_qsum + (size_t)(tok0 + tloc) * DD + dbase;
            const float* xp = x + (size_t)(tok0 + tloc) * DD + dbase;
            float* op = out + (size_t)(tok0 + tloc) * DD + dbase;
            float s = 0.f;
            #pragma unroll 4
            for (int j = 0; j < 128; j += 4) {
                float4 q = *(const float4*)(qv + j);
                int dp = (dbase + j) >> 1;
                float2* p01 = (float2*)&res[dp * RP + tloc * 2];
                float2* p23 = (float2*)&res[(dp + 1) * RP + tloc * 2];
                float2 r01 = *p01, r23 = *p23;
                float r0 = r01.x - q.x, r1 = r01.y - q.y;
                float r2 = r23.x - q.z, r3 = r23.y - q.w;
                *p01 = make_float2(r0, r1);
                *p23 = make_float2(r2, r3);
                s += r0 * r0; s += r1 * r1; s += r2 * r2; s += r3 * r3;

                float4 qa;
                if (l == 0) {
                    qa = q;
                } else {
                    float4 o = *(const float4*)(qs + j);
                    qa.x = o.x + q.x; qa.y = o.y + q.y;
                    qa.z = o.z + q.z; qa.w = o.w + q.w;
                }
                *(float4*)(qs + j) = qa;

                if (l == QL - 1) {
                    float4 xv = *(const float4*)(xp + j);
                    float4 ov;
                    ov.x = xv.x + (qa.x - xv.x);
                    ov.y = xv.y + (qa.y - xv.y);
                    ov.z = xv.z + (qa.z - xv.z);
                    ov.w = xv.w + (qa.w - xv.w);
                    *(float4*)(op + j) = ov;
                }
            }
            rsqp[tsub * 64 + tloc] = s;
        }
        __syncthreads();
        if (tid < MT)
            rsq[tid] = ((rsqp[tid] + rsqp[64 + tid]) + rsqp[128 + tid]) + rsqp[192 + tid];
        __syncthreads();
        if (tid == 0) {
            double cs = 0.0;
            for (int t = 0; t < MT; ++t) cs += (double)rsq[t];
            atomicAdd(&g_commit[l], cs);
        }
    }
}

// ---------------------------------------------------------------------------
__global__ void rvq_fin(float* __restrict__ out) {
    __shared__ double red[256];
    const int tid = threadIdx.x;
    double psum = 0.0;
    for (int l = 0; l < QL; ++l) {
        double s = 0.0;
        for (int k = tid; k < KC; k += 256) {
            double p = (double)g_cnt[l * KC + k] / (double)NTOK;
            s += p * log(p + 1e-10);
        }
        red[tid] = s;
        __syncthreads();
        for (int off = 128; off > 0; off >>= 1) {
            if (tid < off) red[tid] += red[tid + off];
            __syncthreads();
        }
        if (tid == 0) psum += exp(-red[0]);
        __syncthreads();
    }
    if (tid == 0) {
        double closs = 0.0;
        for (int l = 0; l < QL; ++l)
            closs += g_commit[l] / ((double)NTOK * (double)DD);
        out[SCLOFF]     = (float)(0.25 * closs);
        out[SCLOFF + 1] = (float)(psum / (double)QL);
    }
}

// ---------------------------------------------------------------------------
extern "C" void kernel_launch(void* const* d_in, const int* in_sizes, int n_in,
                              void* d_out, int out_size) {
    const float* x  = (const float*)d_in[0];
    const float* cb = (const float*)d_in[1];
    float* out = (float*)d_out;

    const int smem = ((DD / 2) * RP + (DS / 2) * PSTR +
                      16 * 64 * 2 + 4 * 64 + 64 + 64) * 4;
    cudaFuncSetAttribute(rvq_main, cudaFuncAttributeMaxDynamicSharedMemorySize, smem);

    rvq_prep<<<(QL * KC + 255) / 256, 256>>>(cb);
    rvq_main<<<NCTA, 256, smem>>>(x, cb, out);
    rvq_fin<<<1, 256>>>(out);
}